// round 2
// baseline (speedup 1.0000x reference)
#include <cuda_runtime.h>
#include <math.h>

// Problem constants (fixed by the dataset)
#define NNODES 100000
#define HDIM   128
#define NGRAPH 256
#define MTILE  64
#define EMAX   1600000

typedef unsigned long long ull;

// ---------------- scratch (device globals: allocation-free) ----------------
__device__ float g_bufA[NNODES * HDIM];
__device__ float g_bufB[NNODES * HDIM];
__device__ float g_bufC[NNODES * HDIM];
__device__ float g_invs[NNODES];
__device__ float g_pooled[NGRAPH * HDIM];
__device__ int   g_cnt[NNODES];
__device__ int   g_off[NNODES + 1];
__device__ int   g_cursor[NNODES];
__device__ int   g_bsum[256];
__device__ int   g_srcsorted[EMAX];

#define FFMA2(d, a, b, c) \
    asm("fma.rn.f32x2 %0, %1, %2, %3;" : "=l"(d) : "l"(a), "l"(b), "l"(c))

// ---------------- CSR build ----------------
__global__ void k_zero_int(int* v, int n) {
    int i = blockIdx.x * blockDim.x + threadIdx.x;
    if (i < n) v[i] = 0;
}

__global__ void k_hist(const int* __restrict__ dst, int* cnt, int E) {
    int e = blockIdx.x * blockDim.x + threadIdx.x;
    if (e < E) atomicAdd(&cnt[dst[e]], 1);
}

// per-block exclusive scan (1024 elems/block) + block sums
__global__ void k_scan1(const int* __restrict__ cnt, int* __restrict__ excl,
                        int* __restrict__ bsum, int n)
{
    __shared__ int sh[1024];
    int i = blockIdx.x * 1024 + threadIdx.x;
    int v = (i < n) ? cnt[i] : 0;
    sh[threadIdx.x] = v;
    __syncthreads();
    #pragma unroll
    for (int ofs = 1; ofs < 1024; ofs <<= 1) {
        int t = (threadIdx.x >= ofs) ? sh[threadIdx.x - ofs] : 0;
        __syncthreads();
        sh[threadIdx.x] += t;
        __syncthreads();
    }
    if (i < n) excl[i] = sh[threadIdx.x] - v;   // exclusive within block
    if (threadIdx.x == 1023) bsum[blockIdx.x] = sh[1023];
}

__global__ void k_scan2(int* bsum, int nb) {
    if (threadIdx.x == 0 && blockIdx.x == 0) {
        int acc = 0;
        for (int b = 0; b < nb; ++b) { int t = bsum[b]; bsum[b] = acc; acc += t; }
    }
}

__global__ void k_scan3(int* excl, const int* __restrict__ bsum, int n) {
    int i = blockIdx.x * 1024 + threadIdx.x;
    if (i < n) excl[i] += bsum[blockIdx.x];
}

__global__ void k_tail(int* off, int N, int E) {
    if (threadIdx.x == 0 && blockIdx.x == 0) off[N] = E;
}

// invs = rsqrt(cnt+1); cursor = off
__global__ void k_prep(const int* __restrict__ cnt, const int* __restrict__ off,
                       float* invs, int* cursor, int N)
{
    int i = blockIdx.x * blockDim.x + threadIdx.x;
    if (i < N) {
        invs[i] = rsqrtf((float)(cnt[i] + 1));
        cursor[i] = off[i];
    }
}

__global__ void k_fill(const int* __restrict__ esrc, const int* __restrict__ edst,
                       int* cursor, int* __restrict__ srcsorted, int E)
{
    int e = blockIdx.x * blockDim.x + threadIdx.x;
    if (e < E) {
        int d = edst[e];
        int pos = atomicAdd(&cursor[d], 1);
        srcsorted[pos] = esrc[e];
    }
}

// ---------------- GEMM (FFMA2): C = (reluA? relu(A):A)[M,128] @ W[128,128] + bias ----------------
__global__ void gemm_nn(const float* __restrict__ A, const float* __restrict__ W,
                        const float* __restrict__ bias, float* __restrict__ C,
                        int M, int reluA)
{
    extern __shared__ float sm[];
    float* Wsm = sm;               // 128*128 floats (64KB)
    float* A2  = sm + 128 * 128;   // MTILE*128*2 floats, duplicated (64KB)
    const int tid = threadIdx.x;

    #pragma unroll
    for (int i = tid * 4; i < 128 * 128; i += 256 * 4)
        *(float4*)(Wsm + i) = *(const float4*)(W + i);

    const int row0 = blockIdx.x * MTILE;
    #pragma unroll
    for (int i = tid * 4; i < MTILE * 128; i += 256 * 4) {
        int r = i >> 7;
        int c = i & 127;
        int gr = row0 + r;
        float4 v = make_float4(0.f, 0.f, 0.f, 0.f);
        if (gr < M) v = *(const float4*)(A + (size_t)gr * 128 + c);
        if (reluA) {
            v.x = fmaxf(v.x, 0.f); v.y = fmaxf(v.y, 0.f);
            v.z = fmaxf(v.z, 0.f); v.w = fmaxf(v.w, 0.f);
        }
        float* p = A2 + ((size_t)r * 128 + c) * 2;
        *(float4*)p       = make_float4(v.x, v.x, v.y, v.y);
        *(float4*)(p + 4) = make_float4(v.z, v.z, v.w, v.w);
    }
    __syncthreads();

    const int tx = tid & 31;   // cols [tx*4, tx*4+4) as two f32x2
    const int ty = tid >> 5;   // rows [ty*8, ty*8+8)

    ull acc[8][2];
    #pragma unroll
    for (int r = 0; r < 8; ++r) { acc[r][0] = 0ull; acc[r][1] = 0ull; }

    const ulonglong2* Wp = (const ulonglong2*)Wsm;   // row k -> Wp[k*32+tx]
    const ull* Ap = (const ull*)A2;                  // (row,k) -> Ap[row*128+k]

    #pragma unroll 4
    for (int k4 = 0; k4 < 32; ++k4) {
        ulonglong2 w0 = Wp[(k4 * 4 + 0) * 32 + tx];
        ulonglong2 w1 = Wp[(k4 * 4 + 1) * 32 + tx];
        ulonglong2 w2 = Wp[(k4 * 4 + 2) * 32 + tx];
        ulonglong2 w3 = Wp[(k4 * 4 + 3) * 32 + tx];
        #pragma unroll
        for (int r = 0; r < 8; ++r) {
            const ull* ap = Ap + ((ty * 8 + r) * 128 + k4 * 4);
            ull a0 = ap[0], a1 = ap[1], a2 = ap[2], a3 = ap[3];
            FFMA2(acc[r][0], a0, w0.x, acc[r][0]);
            FFMA2(acc[r][1], a0, w0.y, acc[r][1]);
            FFMA2(acc[r][0], a1, w1.x, acc[r][0]);
            FFMA2(acc[r][1], a1, w1.y, acc[r][1]);
            FFMA2(acc[r][0], a2, w2.x, acc[r][0]);
            FFMA2(acc[r][1], a2, w2.y, acc[r][1]);
            FFMA2(acc[r][0], a3, w3.x, acc[r][0]);
            FFMA2(acc[r][1], a3, w3.y, acc[r][1]);
        }
    }

    float4 b = *(const float4*)(bias + tx * 4);
    const int gr0 = row0 + ty * 8;
    #pragma unroll
    for (int r = 0; r < 8; ++r) {
        int gr = gr0 + r;
        if (gr < M) {
            float x0, x1, x2, x3;
            asm("mov.b64 {%0,%1}, %2;" : "=f"(x0), "=f"(x1) : "l"(acc[r][0]));
            asm("mov.b64 {%0,%1}, %2;" : "=f"(x2), "=f"(x3) : "l"(acc[r][1]));
            *(float4*)(C + (size_t)gr * 128 + tx * 4) =
                make_float4(x0 + b.x, x1 + b.y, x2 + b.z, x3 + b.w);
        }
    }
}

// ---------------- CSR gather aggregation (self-loop fused) ----------------
// out[d,:] = invs[d] * ( hw[d,:]*invs[d] + sum_{e: dst=d} hw[src_e,:]*invs[src_e] )
__global__ void k_aggregate(const float* __restrict__ hw, const int* __restrict__ srcs,
                            const int* __restrict__ off, const float* __restrict__ invs,
                            float* __restrict__ out, int N)
{
    __shared__ int   s_src[128];
    __shared__ float s_inv[128];
    int node = blockIdx.x;
    int t = threadIdx.x;   // feature index 0..127
    int beg = off[node], end = off[node + 1];
    float invd = invs[node];
    float acc  = hw[(size_t)node * 128 + t] * invd;   // self-loop term
    float acc2 = 0.f;

    for (int base = beg; base < end; base += 128) {
        int m = end - base;
        if (m > 128) m = 128;
        __syncthreads();
        if (t < m) {
            int s = srcs[base + t];
            s_src[t] = s;
            s_inv[t] = invs[s];
        }
        __syncthreads();
        int j = 0;
        for (; j + 1 < m; j += 2) {
            acc  = fmaf(hw[(size_t)s_src[j]     * 128 + t], s_inv[j],     acc);
            acc2 = fmaf(hw[(size_t)s_src[j + 1] * 128 + t], s_inv[j + 1], acc2);
        }
        if (j < m)
            acc = fmaf(hw[(size_t)s_src[j] * 128 + t], s_inv[j], acc);
    }
    out[(size_t)node * 128 + t] = (acc + acc2) * invd;
}

// ---------------- pooling ----------------
__global__ void k_zero(float* v, int n) {
    int i = blockIdx.x * blockDim.x + threadIdx.x;
    if (i < n) v[i] = 0.f;
}

__global__ void k_pool(const float* __restrict__ h, const int* __restrict__ batch,
                       float* __restrict__ pooled, int N)
{
    int w = (blockIdx.x * blockDim.x + threadIdx.x) >> 5;
    if (w >= N) return;
    int lane = threadIdx.x & 31;
    int g = __ldg(batch + w);
    float4 v = *(const float4*)(h + (size_t)w * 128 + lane * 4);
    float* p = pooled + (size_t)g * 128 + lane * 4;
    asm volatile("red.global.add.v4.f32 [%0], {%1,%2,%3,%4};"
                 :: "l"(p), "f"(v.x), "f"(v.y), "f"(v.z), "f"(v.w)
                 : "memory");
}

// ---------------- decoder ----------------
__global__ void k_decoder(const float* __restrict__ pooled,
                          const float* __restrict__ w1, const float* __restrict__ b1,
                          const float* __restrict__ w2, const float* __restrict__ b2,
                          float* __restrict__ out)
{
    __shared__ float p[128];
    __shared__ float d1[128];
    int g = blockIdx.x;
    int t = threadIdx.x;
    p[t] = pooled[g * 128 + t];
    __syncthreads();
    float s = b1[t];
    #pragma unroll 8
    for (int k = 0; k < 128; ++k) s = fmaf(p[k], w1[k * 128 + t], s);
    d1[t] = fmaxf(s, 0.f);
    __syncthreads();
    if (t < 10) {
        float s2 = b2[t];
        #pragma unroll 8
        for (int j = 0; j < 128; ++j) s2 = fmaf(d1[j], w2[j * 10 + t], s2);
        out[g * 10 + t] = s2;
    }
}

// ---------------- driver ----------------
extern "C" void kernel_launch(void* const* d_in, const int* in_sizes, int n_in,
                              void* d_out, int out_size)
{
    const float* x      = (const float*)d_in[0];
    const int*   ei     = (const int*)d_in[1];
    const int*   batch  = (const int*)d_in[3];
    const float* enc_w1 = (const float*)d_in[4];
    const float* enc_b1 = (const float*)d_in[5];
    const float* enc_w2 = (const float*)d_in[6];
    const float* enc_b2 = (const float*)d_in[7];
    const float* conv_w = (const float*)d_in[8];
    const float* conv_b = (const float*)d_in[9];
    const float* dec_w1 = (const float*)d_in[10];
    const float* dec_b1 = (const float*)d_in[11];
    const float* dec_w2 = (const float*)d_in[12];
    const float* dec_b2 = (const float*)d_in[13];

    const int N = in_sizes[0] / HDIM;
    const int E = in_sizes[1] / 2;
    const int G = out_size / 10;

    float *bufA, *bufB, *bufC, *invs, *pooled;
    int *cnt, *off, *cursor, *bsum, *srcsorted;
    cudaGetSymbolAddress((void**)&bufA, g_bufA);
    cudaGetSymbolAddress((void**)&bufB, g_bufB);
    cudaGetSymbolAddress((void**)&bufC, g_bufC);
    cudaGetSymbolAddress((void**)&invs, g_invs);
    cudaGetSymbolAddress((void**)&pooled, g_pooled);
    cudaGetSymbolAddress((void**)&cnt, g_cnt);
    cudaGetSymbolAddress((void**)&off, g_off);
    cudaGetSymbolAddress((void**)&cursor, g_cursor);
    cudaGetSymbolAddress((void**)&bsum, g_bsum);
    cudaGetSymbolAddress((void**)&srcsorted, g_srcsorted);

    const int* esrc = ei;
    const int* edst = ei + E;

    // ---- CSR build + degree normalization ----
    const int nb = (N + 1023) / 1024;
    k_zero_int<<<(N + 255) / 256, 256>>>(cnt, N);
    k_hist<<<(E + 255) / 256, 256>>>(edst, cnt, E);
    k_scan1<<<nb, 1024>>>(cnt, off, bsum, N);
    k_scan2<<<1, 32>>>(bsum, nb);
    k_scan3<<<nb, 1024>>>(off, bsum, N);
    k_tail<<<1, 32>>>(off, N, E);
    k_prep<<<(N + 255) / 256, 256>>>(cnt, off, invs, cursor, N);
    k_fill<<<(E + 255) / 256, 256>>>(esrc, edst, cursor, srcsorted, E);

    // ---- GEMM config ----
    const int gblocks = (N + MTILE - 1) / MTILE;
    const size_t smem = (128 * 128 + MTILE * 128 * 2) * sizeof(float);
    cudaFuncSetAttribute(gemm_nn, cudaFuncAttributeMaxDynamicSharedMemorySize, (int)smem);

    // encoder
    gemm_nn<<<gblocks, 256, smem>>>(x, enc_w1, enc_b1, bufC, N, 0);
    gemm_nn<<<gblocks, 256, smem>>>(bufC, enc_w2, enc_b2, bufA, N, 1);

    float* hcur  = bufA;
    float* hnext = bufC;
    float* hw    = bufB;

    for (int l = 0; l < 3; ++l) {
        gemm_nn<<<gblocks, 256, smem>>>(hcur, conv_w + (size_t)l * 128 * 128,
                                        conv_b + (size_t)l * 128, hw, N, l > 0 ? 1 : 0);
        k_aggregate<<<N, 128>>>(hw, srcsorted, off, invs, hnext, N);
        float* t = hcur; hcur = hnext; hnext = t;
    }

    // global add pool
    k_zero<<<(G * 128 + 255) / 256, 256>>>(pooled, G * 128);
    k_pool<<<(N * 32 + 255) / 256, 256>>>(hcur, batch, pooled, N);

    // decoder
    k_decoder<<<G, 128>>>(pooled, dec_w1, dec_b1, dec_w2, dec_b2, (float*)d_out);
}

// round 3
// speedup vs baseline: 1.2829x; 1.2829x over previous
#include <cuda_runtime.h>
#include <math.h>

// Problem constants (fixed by the dataset)
#define NNODES 100000
#define HDIM   128
#define NGRAPH 256
#define MTILE  64
#define EMAX   1600000

// ---------------- scratch (device globals: allocation-free) ----------------
__device__ float  g_bufA[NNODES * HDIM];
__device__ float  g_bufB[NNODES * HDIM];
__device__ float  g_bufC[NNODES * HDIM];
__device__ float  g_invs[NNODES];
__device__ float  g_pooled[NGRAPH * HDIM];
__device__ int    g_cnt[NNODES];
__device__ int    g_off[NNODES + 1];
__device__ int    g_cursor[NNODES];
__device__ int    g_bsum[1024];
__device__ float2 g_edge[EMAX];   // {__int_as_float(src), invs[src]}

// ---------------- CSR build ----------------
// launch 0: zero cnt AND pooled in one kernel
__global__ void k_zeros(int* cnt, float* pooled, int N, int P) {
    int i = blockIdx.x * blockDim.x + threadIdx.x;
    if (i < N) cnt[i] = 0;
    if (i < P) pooled[i] = 0.f;
}

// launch 1
__global__ void k_hist(const int* __restrict__ dst, int* cnt, int E) {
    int e = blockIdx.x * blockDim.x + threadIdx.x;
    if (e < E) atomicAdd(&cnt[dst[e]], 1);
}

// launch 2: per-1024-block exclusive scan, block totals to bsum
__global__ void k_scan1(const int* __restrict__ cnt, int* __restrict__ off,
                        int* __restrict__ bsum, int n)
{
    __shared__ int sh[1024];
    int i = blockIdx.x * 1024 + threadIdx.x;
    int v = (i < n) ? cnt[i] : 0;
    sh[threadIdx.x] = v;
    __syncthreads();
    #pragma unroll
    for (int ofs = 1; ofs < 1024; ofs <<= 1) {
        int t = (threadIdx.x >= ofs) ? sh[threadIdx.x - ofs] : 0;
        __syncthreads();
        sh[threadIdx.x] += t;
        __syncthreads();
    }
    if (i < n) off[i] = sh[threadIdx.x] - v;   // exclusive within block
    if (threadIdx.x == 1023) bsum[blockIdx.x] = sh[1023];
}

// launch 3: parallel exclusive scan of block sums (nb <= 1024)
__global__ void k_scan2(int* bsum, int nb) {
    __shared__ int sh[1024];
    int t = threadIdx.x;
    int v = (t < nb) ? bsum[t] : 0;
    sh[t] = v;
    __syncthreads();
    #pragma unroll
    for (int ofs = 1; ofs < 1024; ofs <<= 1) {
        int u = (t >= ofs) ? sh[t - ofs] : 0;
        __syncthreads();
        sh[t] += u;
        __syncthreads();
    }
    if (t < nb) bsum[t] = sh[t] - v;
}

// launch 4: finalize off, cursor, invs, off[N]
__global__ void k_scan3_prep(int* __restrict__ off, const int* __restrict__ bsum,
                             const int* __restrict__ cnt, int* __restrict__ cursor,
                             float* __restrict__ invs, int N, int E)
{
    int i = blockIdx.x * 1024 + threadIdx.x;
    if (i < N) {
        int o = off[i] + bsum[blockIdx.x];
        off[i] = o;
        cursor[i] = o;
        invs[i] = rsqrtf((float)(cnt[i] + 1));
    }
    if (i == 0) off[N] = E;
}

// (after encoder gemms) fill edge records {src, invs[src]} sorted by dst
__global__ void k_fill(const int* __restrict__ esrc, const int* __restrict__ edst,
                       const float* __restrict__ invs, int* cursor,
                       float2* __restrict__ edge, int E)
{
    int e = blockIdx.x * blockDim.x + threadIdx.x;
    if (e < E) {
        int d = edst[e];
        int s = esrc[e];
        int pos = atomicAdd(&cursor[d], 1);
        edge[pos] = make_float2(__int_as_float(s), invs[s]);
    }
}

// ---------------- GEMM (round-1 proven): C = (reluA? relu(A):A) @ W + bias ----------------
__global__ void gemm_nn(const float* __restrict__ A, const float* __restrict__ W,
                        const float* __restrict__ bias, float* __restrict__ C,
                        int M, int reluA)
{
    extern __shared__ float sm[];
    float* Wsm = sm;               // 128*128 floats
    float* Asm = sm + 128 * 128;   // MTILE*128 floats
    const int tid = threadIdx.x;

    #pragma unroll
    for (int i = tid * 4; i < 128 * 128; i += 256 * 4)
        *(float4*)(Wsm + i) = *(const float4*)(W + i);

    const int row0 = blockIdx.x * MTILE;
    #pragma unroll
    for (int i = tid * 4; i < MTILE * 128; i += 256 * 4) {
        int r = i >> 7;
        int c = i & 127;
        int gr = row0 + r;
        float4 v = make_float4(0.f, 0.f, 0.f, 0.f);
        if (gr < M) v = *(const float4*)(A + (size_t)gr * 128 + c);
        if (reluA) {
            v.x = fmaxf(v.x, 0.f); v.y = fmaxf(v.y, 0.f);
            v.z = fmaxf(v.z, 0.f); v.w = fmaxf(v.w, 0.f);
        }
        *(float4*)(Asm + i) = v;
    }
    __syncthreads();

    const int tx = tid & 31;
    const int ty = tid >> 5;

    float acc[8][4];
    #pragma unroll
    for (int r = 0; r < 8; ++r)
        #pragma unroll
        for (int c = 0; c < 4; ++c) acc[r][c] = 0.f;

    const float4* Wv = (const float4*)Wsm;

    #pragma unroll 4
    for (int k4 = 0; k4 < 32; ++k4) {
        float4 w0 = Wv[(k4 * 4 + 0) * 32 + tx];
        float4 w1 = Wv[(k4 * 4 + 1) * 32 + tx];
        float4 w2 = Wv[(k4 * 4 + 2) * 32 + tx];
        float4 w3 = Wv[(k4 * 4 + 3) * 32 + tx];
        #pragma unroll
        for (int r = 0; r < 8; ++r) {
            float4 a = *(const float4*)(Asm + (ty * 8 + r) * 128 + k4 * 4);
            acc[r][0] = fmaf(a.x, w0.x, acc[r][0]);
            acc[r][0] = fmaf(a.y, w1.x, acc[r][0]);
            acc[r][0] = fmaf(a.z, w2.x, acc[r][0]);
            acc[r][0] = fmaf(a.w, w3.x, acc[r][0]);
            acc[r][1] = fmaf(a.x, w0.y, acc[r][1]);
            acc[r][1] = fmaf(a.y, w1.y, acc[r][1]);
            acc[r][1] = fmaf(a.z, w2.y, acc[r][1]);
            acc[r][1] = fmaf(a.w, w3.y, acc[r][1]);
            acc[r][2] = fmaf(a.x, w0.z, acc[r][2]);
            acc[r][2] = fmaf(a.y, w1.z, acc[r][2]);
            acc[r][2] = fmaf(a.z, w2.z, acc[r][2]);
            acc[r][2] = fmaf(a.w, w3.z, acc[r][2]);
            acc[r][3] = fmaf(a.x, w0.w, acc[r][3]);
            acc[r][3] = fmaf(a.y, w1.w, acc[r][3]);
            acc[r][3] = fmaf(a.z, w2.w, acc[r][3]);
            acc[r][3] = fmaf(a.w, w3.w, acc[r][3]);
        }
    }

    float4 b = *(const float4*)(bias + tx * 4);
    const int gr0 = row0 + ty * 8;
    #pragma unroll
    for (int r = 0; r < 8; ++r) {
        int gr = gr0 + r;
        if (gr < M) {
            float4 o;
            o.x = acc[r][0] + b.x;
            o.y = acc[r][1] + b.y;
            o.z = acc[r][2] + b.z;
            o.w = acc[r][3] + b.w;
            *(float4*)(C + (size_t)gr * 128 + tx * 4) = o;
        }
    }
}

// ---------------- CSR gather aggregation v2 (no smem, MLP=4, fused self-loop) ----------------
// out[d,:] = invs[d] * ( hw[d,:]*invs[d] + sum_e hw[src_e,:]*invs[src_e] )
__global__ void k_aggregate(const float* __restrict__ hw, const float2* __restrict__ edge,
                            const int* __restrict__ off, const float* __restrict__ invs,
                            float* __restrict__ out, int N)
{
    int node = blockIdx.x;
    int t = threadIdx.x;                 // feature 0..127
    int beg = __ldg(off + node), end = __ldg(off + node + 1);
    float invd = __ldg(invs + node);
    float acc0 = hw[(size_t)node * 128 + t] * invd;    // self-loop term
    float acc1 = 0.f, acc2 = 0.f, acc3 = 0.f;

    int j = beg;
    for (; j + 4 <= end; j += 4) {
        float2 e0 = __ldg(edge + j);
        float2 e1 = __ldg(edge + j + 1);
        float2 e2 = __ldg(edge + j + 2);
        float2 e3 = __ldg(edge + j + 3);
        float v0 = __ldg(hw + (size_t)__float_as_int(e0.x) * 128 + t);
        float v1 = __ldg(hw + (size_t)__float_as_int(e1.x) * 128 + t);
        float v2 = __ldg(hw + (size_t)__float_as_int(e2.x) * 128 + t);
        float v3 = __ldg(hw + (size_t)__float_as_int(e3.x) * 128 + t);
        acc0 = fmaf(v0, e0.y, acc0);
        acc1 = fmaf(v1, e1.y, acc1);
        acc2 = fmaf(v2, e2.y, acc2);
        acc3 = fmaf(v3, e3.y, acc3);
    }
    for (; j < end; ++j) {
        float2 e0 = __ldg(edge + j);
        acc0 = fmaf(__ldg(hw + (size_t)__float_as_int(e0.x) * 128 + t), e0.y, acc0);
    }
    out[(size_t)node * 128 + t] = ((acc0 + acc1) + (acc2 + acc3)) * invd;
}

// ---------------- pooling ----------------
__global__ void k_pool(const float* __restrict__ h, const int* __restrict__ batch,
                       float* __restrict__ pooled, int N)
{
    int w = (blockIdx.x * blockDim.x + threadIdx.x) >> 5;
    if (w >= N) return;
    int lane = threadIdx.x & 31;
    int g = __ldg(batch + w);
    float4 v = *(const float4*)(h + (size_t)w * 128 + lane * 4);
    float* p = pooled + (size_t)g * 128 + lane * 4;
    asm volatile("red.global.add.v4.f32 [%0], {%1,%2,%3,%4};"
                 :: "l"(p), "f"(v.x), "f"(v.y), "f"(v.z), "f"(v.w)
                 : "memory");
}

// ---------------- decoder ----------------
__global__ void k_decoder(const float* __restrict__ pooled,
                          const float* __restrict__ w1, const float* __restrict__ b1,
                          const float* __restrict__ w2, const float* __restrict__ b2,
                          float* __restrict__ out)
{
    __shared__ float p[128];
    __shared__ float d1[128];
    int g = blockIdx.x;
    int t = threadIdx.x;
    p[t] = pooled[g * 128 + t];
    __syncthreads();
    float s = b1[t];
    #pragma unroll 8
    for (int k = 0; k < 128; ++k) s = fmaf(p[k], w1[k * 128 + t], s);
    d1[t] = fmaxf(s, 0.f);
    __syncthreads();
    if (t < 10) {
        float s2 = b2[t];
        #pragma unroll 8
        for (int j = 0; j < 128; ++j) s2 = fmaf(d1[j], w2[j * 10 + t], s2);
        out[g * 10 + t] = s2;
    }
}

// ---------------- driver ----------------
extern "C" void kernel_launch(void* const* d_in, const int* in_sizes, int n_in,
                              void* d_out, int out_size)
{
    const float* x      = (const float*)d_in[0];
    const int*   ei     = (const int*)d_in[1];
    const int*   batch  = (const int*)d_in[3];
    const float* enc_w1 = (const float*)d_in[4];
    const float* enc_b1 = (const float*)d_in[5];
    const float* enc_w2 = (const float*)d_in[6];
    const float* enc_b2 = (const float*)d_in[7];
    const float* conv_w = (const float*)d_in[8];
    const float* conv_b = (const float*)d_in[9];
    const float* dec_w1 = (const float*)d_in[10];
    const float* dec_b1 = (const float*)d_in[11];
    const float* dec_w2 = (const float*)d_in[12];
    const float* dec_b2 = (const float*)d_in[13];

    const int N = in_sizes[0] / HDIM;
    const int E = in_sizes[1] / 2;
    const int G = out_size / 10;

    float *bufA, *bufB, *bufC, *invs, *pooled;
    int *cnt, *off, *cursor, *bsum;
    float2* edge;
    cudaGetSymbolAddress((void**)&bufA, g_bufA);
    cudaGetSymbolAddress((void**)&bufB, g_bufB);
    cudaGetSymbolAddress((void**)&bufC, g_bufC);
    cudaGetSymbolAddress((void**)&invs, g_invs);
    cudaGetSymbolAddress((void**)&pooled, g_pooled);
    cudaGetSymbolAddress((void**)&cnt, g_cnt);
    cudaGetSymbolAddress((void**)&off, g_off);
    cudaGetSymbolAddress((void**)&cursor, g_cursor);
    cudaGetSymbolAddress((void**)&bsum, g_bsum);
    cudaGetSymbolAddress((void**)&edge, g_edge);

    const int* esrc = ei;
    const int* edst = ei + E;

    // ---- CSR build: exactly 5 launches (indices 0..4) so ncu -s5 lands on gemm ----
    const int nb = (N + 1023) / 1024;
    k_zeros<<<(N + 255) / 256, 256>>>(cnt, pooled, N, G * 128);             // 0
    k_hist<<<(E + 255) / 256, 256>>>(edst, cnt, E);                          // 1
    k_scan1<<<nb, 1024>>>(cnt, off, bsum, N);                                // 2
    k_scan2<<<1, 1024>>>(bsum, nb);                                          // 3
    k_scan3_prep<<<nb, 1024>>>(off, bsum, cnt, cursor, invs, N, E);          // 4

    // ---- GEMM config ----
    const int gblocks = (N + MTILE - 1) / MTILE;
    const size_t smem = (128 * 128 + MTILE * 128) * sizeof(float);
    cudaFuncSetAttribute(gemm_nn, cudaFuncAttributeMaxDynamicSharedMemorySize, (int)smem);

    // encoder (launch 5 -> profiled by ncu)
    gemm_nn<<<gblocks, 256, smem>>>(x, enc_w1, enc_b1, bufC, N, 0);          // 5
    gemm_nn<<<gblocks, 256, smem>>>(bufC, enc_w2, enc_b2, bufA, N, 1);       // 6

    // edge records (needs invs; only needed before first aggregate)
    k_fill<<<(E + 255) / 256, 256>>>(esrc, edst, invs, cursor, edge, E);     // 7

    float* hcur  = bufA;
    float* hnext = bufC;
    float* hw    = bufB;

    for (int l = 0; l < 3; ++l) {
        gemm_nn<<<gblocks, 256, smem>>>(hcur, conv_w + (size_t)l * 128 * 128,
                                        conv_b + (size_t)l * 128, hw, N, l > 0 ? 1 : 0);
        k_aggregate<<<N, 128>>>(hw, edge, off, invs, hnext, N);
        float* t = hcur; hcur = hnext; hnext = t;
    }

    // global add pool (pooled zeroed at launch 0)
    k_pool<<<(N * 32 + 255) / 256, 256>>>(hcur, batch, pooled, N);

    // decoder
    k_decoder<<<G, 128>>>(pooled, dec_w1, dec_b1, dec_w2, dec_b2, (float*)d_out);
}

// round 4
// speedup vs baseline: 1.4093x; 1.0985x over previous
#include <cuda_runtime.h>
#include <math.h>

// Problem constants (fixed by the dataset)
#define NNODES 100000
#define HDIM   128
#define NGRAPH 256
#define GTILE  128          // GEMM CTA tile (M)
#define EMAX   1600000
#define SMSTRIDE 132        // padded smem row stride (floats) -> conflict-free frags

// ---------------- scratch (device globals: allocation-free) ----------------
__device__ float  g_bufA[NNODES * HDIM];
__device__ float  g_bufB[NNODES * HDIM];
__device__ float  g_bufC[NNODES * HDIM];
__device__ float  g_invs[NNODES];
__device__ float  g_pooled[NGRAPH * HDIM];
__device__ int    g_cnt[NNODES];
__device__ int    g_off[NNODES + 1];
__device__ int    g_cursor[NNODES];
__device__ int    g_bsum[1024];
__device__ float2 g_edge[EMAX];   // {__int_as_float(src), invs[src]}

__device__ __forceinline__ unsigned f2tf32(float x) {
    unsigned r;
    asm("cvt.rna.tf32.f32 %0, %1;" : "=r"(r) : "f"(x));
    return r;
}

// ---------------- CSR build ----------------
__global__ void k_zeros(int* cnt, float* pooled, int N, int P) {
    int i = blockIdx.x * blockDim.x + threadIdx.x;
    if (i < N) cnt[i] = 0;
    if (i < P) pooled[i] = 0.f;
}

__global__ void k_hist(const int* __restrict__ dst, int* cnt, int E) {
    int e = blockIdx.x * blockDim.x + threadIdx.x;
    if (e < E) atomicAdd(&cnt[dst[e]], 1);
}

__global__ void k_scan1(const int* __restrict__ cnt, int* __restrict__ off,
                        int* __restrict__ bsum, int n)
{
    __shared__ int sh[1024];
    int i = blockIdx.x * 1024 + threadIdx.x;
    int v = (i < n) ? cnt[i] : 0;
    sh[threadIdx.x] = v;
    __syncthreads();
    #pragma unroll
    for (int ofs = 1; ofs < 1024; ofs <<= 1) {
        int t = (threadIdx.x >= ofs) ? sh[threadIdx.x - ofs] : 0;
        __syncthreads();
        sh[threadIdx.x] += t;
        __syncthreads();
    }
    if (i < n) off[i] = sh[threadIdx.x] - v;
    if (threadIdx.x == 1023) bsum[blockIdx.x] = sh[1023];
}

__global__ void k_scan2(int* bsum, int nb) {
    __shared__ int sh[1024];
    int t = threadIdx.x;
    int v = (t < nb) ? bsum[t] : 0;
    sh[t] = v;
    __syncthreads();
    #pragma unroll
    for (int ofs = 1; ofs < 1024; ofs <<= 1) {
        int u = (t >= ofs) ? sh[t - ofs] : 0;
        __syncthreads();
        sh[t] += u;
        __syncthreads();
    }
    if (t < nb) bsum[t] = sh[t] - v;
}

__global__ void k_scan3_prep(int* __restrict__ off, const int* __restrict__ bsum,
                             const int* __restrict__ cnt, int* __restrict__ cursor,
                             float* __restrict__ invs, int N, int E)
{
    int i = blockIdx.x * 1024 + threadIdx.x;
    if (i < N) {
        int o = off[i] + bsum[blockIdx.x];
        off[i] = o;
        cursor[i] = o;
        invs[i] = rsqrtf((float)(cnt[i] + 1));
    }
    if (i == 0) off[N] = E;
}

__global__ void k_fill(const int* __restrict__ esrc, const int* __restrict__ edst,
                       const float* __restrict__ invs, int* cursor,
                       float2* __restrict__ edge, int E)
{
    int e = blockIdx.x * blockDim.x + threadIdx.x;
    if (e < E) {
        int d = edst[e];
        int s = esrc[e];
        int pos = atomicAdd(&cursor[d], 1);
        edge[pos] = make_float2(__int_as_float(s), invs[s]);
    }
}

// ---------------- tf32 tensor-core GEMM: C = (reluA? relu(A):A)[M,128] @ W[128,128] + bias ----------------
// CTA: 256 threads (8 warps), tile 128(M) x 128(N), K=128 in 16 steps of k8.
// Warp w computes rows [w*16, w*16+16), all 128 cols (16 m16n8 tiles).
__global__ void gemm_tf32(const float* __restrict__ A, const float* __restrict__ W,
                          const float* __restrict__ bias, float* __restrict__ C,
                          int M, int reluA)
{
    extern __shared__ unsigned sm[];
    unsigned* Ws = sm;                       // [128][SMSTRIDE] tf32 bits
    unsigned* As = sm + 128 * SMSTRIDE;      // [128][SMSTRIDE] tf32 bits
    const int tid = threadIdx.x;

    // stage W (row-major [k][n]) with tf32 RN conversion
    #pragma unroll
    for (int i = tid * 4; i < 128 * 128; i += 256 * 4) {
        int r = i >> 7, c = i & 127;
        float4 v = *(const float4*)(W + i);
        uint4 u;
        u.x = f2tf32(v.x); u.y = f2tf32(v.y); u.z = f2tf32(v.z); u.w = f2tf32(v.w);
        *(uint4*)(Ws + r * SMSTRIDE + c) = u;
    }

    // stage A tile with relu + boundary + tf32 RN conversion
    const int row0 = blockIdx.x * GTILE;
    #pragma unroll
    for (int i = tid * 4; i < 128 * 128; i += 256 * 4) {
        int r = i >> 7, c = i & 127;
        int gr = row0 + r;
        float4 v = make_float4(0.f, 0.f, 0.f, 0.f);
        if (gr < M) v = *(const float4*)(A + (size_t)gr * 128 + c);
        if (reluA) {
            v.x = fmaxf(v.x, 0.f); v.y = fmaxf(v.y, 0.f);
            v.z = fmaxf(v.z, 0.f); v.w = fmaxf(v.w, 0.f);
        }
        uint4 u;
        u.x = f2tf32(v.x); u.y = f2tf32(v.y); u.z = f2tf32(v.z); u.w = f2tf32(v.w);
        *(uint4*)(As + r * SMSTRIDE + c) = u;
    }
    __syncthreads();

    const int warp = tid >> 5;
    const int lane = tid & 31;
    const int gid  = lane >> 2;   // 0..7
    const int tig  = lane & 3;    // 0..3
    const int m0   = warp * 16;

    float acc[16][4];
    #pragma unroll
    for (int t = 0; t < 16; ++t)
        #pragma unroll
        for (int c = 0; c < 4; ++c) acc[t][c] = 0.f;

    const unsigned* Arow0 = As + (m0 + gid) * SMSTRIDE + tig;        // a0/a2 base
    const unsigned* Arow8 = As + (m0 + 8 + gid) * SMSTRIDE + tig;    // a1/a3 base

    #pragma unroll
    for (int ks = 0; ks < 16; ++ks) {
        const int k0 = ks * 8;
        unsigned a0 = Arow0[k0];
        unsigned a1 = Arow8[k0];
        unsigned a2 = Arow0[k0 + 4];
        unsigned a3 = Arow8[k0 + 4];
        const unsigned* Bb0 = Ws + (k0 + tig) * SMSTRIDE + gid;
        const unsigned* Bb1 = Ws + (k0 + 4 + tig) * SMSTRIDE + gid;
        #pragma unroll
        for (int nt = 0; nt < 16; ++nt) {
            unsigned b0 = Bb0[nt * 8];
            unsigned b1 = Bb1[nt * 8];
            asm volatile(
                "mma.sync.aligned.m16n8k8.row.col.f32.tf32.tf32.f32 "
                "{%0,%1,%2,%3}, {%4,%5,%6,%7}, {%8,%9}, {%0,%1,%2,%3};"
                : "+f"(acc[nt][0]), "+f"(acc[nt][1]), "+f"(acc[nt][2]), "+f"(acc[nt][3])
                : "r"(a0), "r"(a1), "r"(a2), "r"(a3), "r"(b0), "r"(b1));
        }
    }

    // epilogue: c0,c1 -> (row=gid, cols 2*tig, 2*tig+1); c2,c3 -> row=gid+8
    const int rA = row0 + m0 + gid;
    const int rB = rA + 8;
    #pragma unroll
    for (int nt = 0; nt < 16; ++nt) {
        int n = nt * 8 + tig * 2;
        float2 b = *(const float2*)(bias + n);
        if (rA < M) {
            float2 o = make_float2(acc[nt][0] + b.x, acc[nt][1] + b.y);
            *(float2*)(C + (size_t)rA * 128 + n) = o;
        }
        if (rB < M) {
            float2 o = make_float2(acc[nt][2] + b.x, acc[nt][3] + b.y);
            *(float2*)(C + (size_t)rB * 128 + n) = o;
        }
    }
}

// ---------------- CSR gather aggregation (no smem, MLP=4, fused self-loop) ----------------
__global__ void k_aggregate(const float* __restrict__ hw, const float2* __restrict__ edge,
                            const int* __restrict__ off, const float* __restrict__ invs,
                            float* __restrict__ out, int N)
{
    int node = blockIdx.x;
    int t = threadIdx.x;
    int beg = __ldg(off + node), end = __ldg(off + node + 1);
    float invd = __ldg(invs + node);
    float acc0 = hw[(size_t)node * 128 + t] * invd;
    float acc1 = 0.f, acc2 = 0.f, acc3 = 0.f;

    int j = beg;
    for (; j + 4 <= end; j += 4) {
        float2 e0 = __ldg(edge + j);
        float2 e1 = __ldg(edge + j + 1);
        float2 e2 = __ldg(edge + j + 2);
        float2 e3 = __ldg(edge + j + 3);
        float v0 = __ldg(hw + (size_t)__float_as_int(e0.x) * 128 + t);
        float v1 = __ldg(hw + (size_t)__float_as_int(e1.x) * 128 + t);
        float v2 = __ldg(hw + (size_t)__float_as_int(e2.x) * 128 + t);
        float v3 = __ldg(hw + (size_t)__float_as_int(e3.x) * 128 + t);
        acc0 = fmaf(v0, e0.y, acc0);
        acc1 = fmaf(v1, e1.y, acc1);
        acc2 = fmaf(v2, e2.y, acc2);
        acc3 = fmaf(v3, e3.y, acc3);
    }
    for (; j < end; ++j) {
        float2 e0 = __ldg(edge + j);
        acc0 = fmaf(__ldg(hw + (size_t)__float_as_int(e0.x) * 128 + t), e0.y, acc0);
    }
    out[(size_t)node * 128 + t] = ((acc0 + acc1) + (acc2 + acc3)) * invd;
}

// ---------------- pooling ----------------
__global__ void k_pool(const float* __restrict__ h, const int* __restrict__ batch,
                       float* __restrict__ pooled, int N)
{
    int w = (blockIdx.x * blockDim.x + threadIdx.x) >> 5;
    if (w >= N) return;
    int lane = threadIdx.x & 31;
    int g = __ldg(batch + w);
    float4 v = *(const float4*)(h + (size_t)w * 128 + lane * 4);
    float* p = pooled + (size_t)g * 128 + lane * 4;
    asm volatile("red.global.add.v4.f32 [%0], {%1,%2,%3,%4};"
                 :: "l"(p), "f"(v.x), "f"(v.y), "f"(v.z), "f"(v.w)
                 : "memory");
}

// ---------------- decoder ----------------
__global__ void k_decoder(const float* __restrict__ pooled,
                          const float* __restrict__ w1, const float* __restrict__ b1,
                          const float* __restrict__ w2, const float* __restrict__ b2,
                          float* __restrict__ out)
{
    __shared__ float p[128];
    __shared__ float d1[128];
    int g = blockIdx.x;
    int t = threadIdx.x;
    p[t] = pooled[g * 128 + t];
    __syncthreads();
    float s = b1[t];
    #pragma unroll 8
    for (int k = 0; k < 128; ++k) s = fmaf(p[k], w1[k * 128 + t], s);
    d1[t] = fmaxf(s, 0.f);
    __syncthreads();
    if (t < 10) {
        float s2 = b2[t];
        #pragma unroll 8
        for (int j = 0; j < 128; ++j) s2 = fmaf(d1[j], w2[j * 10 + t], s2);
        out[g * 10 + t] = s2;
    }
}

// ---------------- driver ----------------
extern "C" void kernel_launch(void* const* d_in, const int* in_sizes, int n_in,
                              void* d_out, int out_size)
{
    const float* x      = (const float*)d_in[0];
    const int*   ei     = (const int*)d_in[1];
    const int*   batch  = (const int*)d_in[3];
    const float* enc_w1 = (const float*)d_in[4];
    const float* enc_b1 = (const float*)d_in[5];
    const float* enc_w2 = (const float*)d_in[6];
    const float* enc_b2 = (const float*)d_in[7];
    const float* conv_w = (const float*)d_in[8];
    const float* conv_b = (const float*)d_in[9];
    const float* dec_w1 = (const float*)d_in[10];
    const float* dec_b1 = (const float*)d_in[11];
    const float* dec_w2 = (const float*)d_in[12];
    const float* dec_b2 = (const float*)d_in[13];

    const int N = in_sizes[0] / HDIM;
    const int E = in_sizes[1] / 2;
    const int G = out_size / 10;

    float *bufA, *bufB, *bufC, *invs, *pooled;
    int *cnt, *off, *cursor, *bsum;
    float2* edge;
    cudaGetSymbolAddress((void**)&bufA, g_bufA);
    cudaGetSymbolAddress((void**)&bufB, g_bufB);
    cudaGetSymbolAddress((void**)&bufC, g_bufC);
    cudaGetSymbolAddress((void**)&invs, g_invs);
    cudaGetSymbolAddress((void**)&pooled, g_pooled);
    cudaGetSymbolAddress((void**)&cnt, g_cnt);
    cudaGetSymbolAddress((void**)&off, g_off);
    cudaGetSymbolAddress((void**)&cursor, g_cursor);
    cudaGetSymbolAddress((void**)&bsum, g_bsum);
    cudaGetSymbolAddress((void**)&edge, g_edge);

    const int* esrc = ei;
    const int* edst = ei + E;

    // ---- CSR build (launches 0..4) ----
    const int nb = (N + 1023) / 1024;
    k_zeros<<<(N + 255) / 256, 256>>>(cnt, pooled, N, G * 128);
    k_hist<<<(E + 255) / 256, 256>>>(edst, cnt, E);
    k_scan1<<<nb, 1024>>>(cnt, off, bsum, N);
    k_scan2<<<1, 1024>>>(bsum, nb);
    k_scan3_prep<<<nb, 1024>>>(off, bsum, cnt, cursor, invs, N, E);

    // ---- GEMM config ----
    const int gblocks = (N + GTILE - 1) / GTILE;
    const size_t smem = 2 * 128 * SMSTRIDE * sizeof(unsigned);   // 132KB
    cudaFuncSetAttribute(gemm_tf32, cudaFuncAttributeMaxDynamicSharedMemorySize, (int)smem);

    // encoder
    gemm_tf32<<<gblocks, 256, smem>>>(x, enc_w1, enc_b1, bufC, N, 0);
    gemm_tf32<<<gblocks, 256, smem>>>(bufC, enc_w2, enc_b2, bufA, N, 1);

    // edge records (needs invs)
    k_fill<<<(E + 255) / 256, 256>>>(esrc, edst, invs, cursor, edge, E);

    float* hcur  = bufA;
    float* hnext = bufC;
    float* hw    = bufB;

    for (int l = 0; l < 3; ++l) {
        gemm_tf32<<<gblocks, 256, smem>>>(hcur, conv_w + (size_t)l * 128 * 128,
                                          conv_b + (size_t)l * 128, hw, N, l > 0 ? 1 : 0);
        k_aggregate<<<N, 128>>>(hw, edge, off, invs, hnext, N);
        float* t = hcur; hcur = hnext; hnext = t;
    }

    // global add pool (pooled zeroed at launch 0)
    k_pool<<<(N * 32 + 255) / 256, 256>>>(hcur, batch, pooled, N);

    // decoder
    k_decoder<<<G, 128>>>(pooled, dec_w1, dec_b1, dec_w2, dec_b2, (float*)d_out);
}

// round 5
// speedup vs baseline: 1.5639x; 1.1097x over previous
#include <cuda_runtime.h>
#include <math.h>

// Problem constants (fixed by the dataset)
#define NNODES 100000
#define HDIM   128
#define NGRAPH 256
#define EMAX   1600000
#define PTILE  32           // rows per GEMM tile
#define ASTRIDE 132         // padded A smem row stride (floats)
#define GEMM_GRID 304       // 2 CTAs/SM on 152-SM GB300
#define GEMM_SMEM (65536 + 2 * PTILE * ASTRIDE * 4)

// ---------------- scratch (device globals: allocation-free) ----------------
__device__ float  g_bufA[NNODES * HDIM];
__device__ float  g_bufB[NNODES * HDIM];
__device__ float  g_bufC[NNODES * HDIM];
__device__ float  g_invs[NNODES];
__device__ float  g_pooled[NGRAPH * HDIM];
__device__ int    g_cnt[NNODES];
__device__ int    g_off[NNODES + 1];
__device__ int    g_cursor[NNODES];
__device__ int    g_bsum[1024];
__device__ float2 g_edge[EMAX];   // {__int_as_float(src), invs[src]}

__device__ __forceinline__ unsigned f2tf32(float x) {
    unsigned r;
    asm("cvt.rna.tf32.f32 %0, %1;" : "=r"(r) : "f"(x));
    return r;
}

// ---------------- CSR build ----------------
__global__ void k_zeros(int* cnt, float* pooled, int N, int P) {
    int i = blockIdx.x * blockDim.x + threadIdx.x;
    if (i < N) cnt[i] = 0;
    if (i < P) pooled[i] = 0.f;
}

__global__ void k_hist(const int* __restrict__ dst, int* cnt, int E) {
    int e = blockIdx.x * blockDim.x + threadIdx.x;
    if (e < E) atomicAdd(&cnt[dst[e]], 1);
}

__global__ void k_scan1(const int* __restrict__ cnt, int* __restrict__ off,
                        int* __restrict__ bsum, int n)
{
    __shared__ int sh[1024];
    int i = blockIdx.x * 1024 + threadIdx.x;
    int v = (i < n) ? cnt[i] : 0;
    sh[threadIdx.x] = v;
    __syncthreads();
    #pragma unroll
    for (int ofs = 1; ofs < 1024; ofs <<= 1) {
        int t = (threadIdx.x >= ofs) ? sh[threadIdx.x - ofs] : 0;
        __syncthreads();
        sh[threadIdx.x] += t;
        __syncthreads();
    }
    if (i < n) off[i] = sh[threadIdx.x] - v;
    if (threadIdx.x == 1023) bsum[blockIdx.x] = sh[1023];
}

__global__ void k_scan2(int* bsum, int nb) {
    __shared__ int sh[1024];
    int t = threadIdx.x;
    int v = (t < nb) ? bsum[t] : 0;
    sh[t] = v;
    __syncthreads();
    #pragma unroll
    for (int ofs = 1; ofs < 1024; ofs <<= 1) {
        int u = (t >= ofs) ? sh[t - ofs] : 0;
        __syncthreads();
        sh[t] += u;
        __syncthreads();
    }
    if (t < nb) bsum[t] = sh[t] - v;
}

__global__ void k_scan3_prep(int* __restrict__ off, const int* __restrict__ bsum,
                             const int* __restrict__ cnt, int* __restrict__ cursor,
                             float* __restrict__ invs, int N, int E)
{
    int i = blockIdx.x * 1024 + threadIdx.x;
    if (i < N) {
        int o = off[i] + bsum[blockIdx.x];
        off[i] = o;
        cursor[i] = o;
        invs[i] = rsqrtf((float)(cnt[i] + 1));
    }
    if (i == 0) off[N] = E;
}

__global__ void k_fill(const int* __restrict__ esrc, const int* __restrict__ edst,
                       const float* __restrict__ invs, int* cursor,
                       float2* __restrict__ edge, int E)
{
    int e = blockIdx.x * blockDim.x + threadIdx.x;
    if (e < E) {
        int d = edst[e];
        int s = esrc[e];
        int pos = atomicAdd(&cursor[d], 1);
        edge[pos] = make_float2(__int_as_float(s), invs[s]);
    }
}

// ---------------- persistent tf32 GEMM ----------------
// C[M,128] = (reluA? relu(A):A) @ W[128,128] + bias
// Grid-stride over 32-row tiles. W staged ONCE per CTA in fragment layout.
// 8 warps: warp -> (mw = warp&1: 16 rows, nw = warp>>1: 32 cols = 4 n-tiles).
__global__ void __launch_bounds__(256, 2)
gemm_tf32p(const float* __restrict__ A, const float* __restrict__ W,
           const float* __restrict__ bias, float* __restrict__ C,
           int M, int ntiles, int reluA)
{
    extern __shared__ char smem_raw[];
    uint2* Wf = (uint2*)smem_raw;                    // [16ks][16nt][32lane] = 64KB
    float* As = (float*)(smem_raw + 65536);          // [2][PTILE][ASTRIDE]
    const int tid = threadIdx.x;

    // ---- stage W fragments once (tf32 RN) ----
    for (int i = tid * 4; i < 128 * 128; i += 256 * 4) {
        int k = i >> 7, n0 = i & 127;
        float4 v = *(const float4*)(W + i);
        int ks = k >> 3, r = k & 7, reg = r >> 2, tig = r & 3;
        #pragma unroll
        for (int j = 0; j < 4; ++j) {
            int n = n0 + j;
            int nt = n >> 3, gid = n & 7;
            unsigned* p = (unsigned*)&Wf[(ks * 16 + nt) * 32 + ((gid << 2) | tig)];
            p[reg] = f2tf32((&v.x)[j]);
        }
    }

    const int warp = tid >> 5;
    const int lane = tid & 31;
    const int gid  = lane >> 2;
    const int tig  = lane & 3;
    const int mw   = warp & 1;
    const int nw   = warp >> 1;

    // ---- prefetch helper (cp.async, 16B chunks; zero-fill OOB rows) ----
    auto prefetch = [&](int tileIdx, int buf) {
        if (tileIdx < ntiles) {
            int row0 = tileIdx * PTILE;
            #pragma unroll
            for (int j = 0; j < 4; ++j) {
                int cid = tid + 256 * j;         // 0..1023
                int row = cid >> 5;              // 0..31
                int c16 = cid & 31;              // 16B chunk in row
                const float* gsrc = A + (size_t)(row0 + row) * 128 + c16 * 4;
                float* dptr = As + buf * (PTILE * ASTRIDE) + row * ASTRIDE + c16 * 4;
                unsigned sa = (unsigned)__cvta_generic_to_shared(dptr);
                int sz = (row0 + row < M) ? 16 : 0;
                if (sz == 0) gsrc = A;           // keep address valid
                asm volatile("cp.async.ca.shared.global [%0], [%1], 16, %2;"
                             :: "r"(sa), "l"(gsrc), "r"(sz));
            }
        }
        asm volatile("cp.async.commit_group;");
    };

    prefetch(blockIdx.x, 0);

    int buf = 0;
    for (int tile = blockIdx.x; tile < ntiles; tile += gridDim.x) {
        prefetch(tile + gridDim.x, buf ^ 1);
        asm volatile("cp.async.wait_group 1;");
        __syncthreads();   // buf ready for all; also covers W staging on iter 0

        const float* Ab = As + buf * (PTILE * ASTRIDE) + (mw * 16) * ASTRIDE;

        float acc[4][4];
        #pragma unroll
        for (int t = 0; t < 4; ++t)
            #pragma unroll
            for (int c = 0; c < 4; ++c) acc[t][c] = 0.f;

        #pragma unroll
        for (int ks = 0; ks < 16; ++ks) {
            const int k0 = ks * 8;
            float a0f = Ab[gid * ASTRIDE + k0 + tig];
            float a1f = Ab[(8 + gid) * ASTRIDE + k0 + tig];
            float a2f = Ab[gid * ASTRIDE + k0 + 4 + tig];
            float a3f = Ab[(8 + gid) * ASTRIDE + k0 + 4 + tig];
            if (reluA) {
                a0f = fmaxf(a0f, 0.f); a1f = fmaxf(a1f, 0.f);
                a2f = fmaxf(a2f, 0.f); a3f = fmaxf(a3f, 0.f);
            }
            unsigned a0 = f2tf32(a0f), a1 = f2tf32(a1f);
            unsigned a2 = f2tf32(a2f), a3 = f2tf32(a3f);
            const uint2* Bp = Wf + (ks * 16 + nw * 4) * 32 + lane;
            #pragma unroll
            for (int t = 0; t < 4; ++t) {
                uint2 b = Bp[t * 32];
                asm volatile(
                    "mma.sync.aligned.m16n8k8.row.col.f32.tf32.tf32.f32 "
                    "{%0,%1,%2,%3}, {%4,%5,%6,%7}, {%8,%9}, {%0,%1,%2,%3};"
                    : "+f"(acc[t][0]), "+f"(acc[t][1]), "+f"(acc[t][2]), "+f"(acc[t][3])
                    : "r"(a0), "r"(a1), "r"(a2), "r"(a3), "r"(b.x), "r"(b.y));
            }
        }

        // epilogue
        const int rA = tile * PTILE + mw * 16 + gid;
        const int rB = rA + 8;
        #pragma unroll
        for (int t = 0; t < 4; ++t) {
            int n = (nw * 4 + t) * 8 + tig * 2;
            float2 b = *(const float2*)(bias + n);
            if (rA < M)
                *(float2*)(C + (size_t)rA * 128 + n) =
                    make_float2(acc[t][0] + b.x, acc[t][1] + b.y);
            if (rB < M)
                *(float2*)(C + (size_t)rB * 128 + n) =
                    make_float2(acc[t][2] + b.x, acc[t][3] + b.y);
        }
        __syncthreads();   // all warps done with buf before it's prefetched into
        buf ^= 1;
    }
}

// ---------------- CSR gather aggregation (no smem, MLP=4, fused self-loop) ----------------
__global__ void k_aggregate(const float* __restrict__ hw, const float2* __restrict__ edge,
                            const int* __restrict__ off, const float* __restrict__ invs,
                            float* __restrict__ out, int N)
{
    int node = blockIdx.x;
    int t = threadIdx.x;
    int beg = __ldg(off + node), end = __ldg(off + node + 1);
    float invd = __ldg(invs + node);
    float acc0 = hw[(size_t)node * 128 + t] * invd;
    float acc1 = 0.f, acc2 = 0.f, acc3 = 0.f;

    int j = beg;
    for (; j + 4 <= end; j += 4) {
        float2 e0 = __ldg(edge + j);
        float2 e1 = __ldg(edge + j + 1);
        float2 e2 = __ldg(edge + j + 2);
        float2 e3 = __ldg(edge + j + 3);
        float v0 = __ldg(hw + (size_t)__float_as_int(e0.x) * 128 + t);
        float v1 = __ldg(hw + (size_t)__float_as_int(e1.x) * 128 + t);
        float v2 = __ldg(hw + (size_t)__float_as_int(e2.x) * 128 + t);
        float v3 = __ldg(hw + (size_t)__float_as_int(e3.x) * 128 + t);
        acc0 = fmaf(v0, e0.y, acc0);
        acc1 = fmaf(v1, e1.y, acc1);
        acc2 = fmaf(v2, e2.y, acc2);
        acc3 = fmaf(v3, e3.y, acc3);
    }
    for (; j < end; ++j) {
        float2 e0 = __ldg(edge + j);
        acc0 = fmaf(__ldg(hw + (size_t)__float_as_int(e0.x) * 128 + t), e0.y, acc0);
    }
    out[(size_t)node * 128 + t] = ((acc0 + acc1) + (acc2 + acc3)) * invd;
}

// ---------------- pooling ----------------
__global__ void k_pool(const float* __restrict__ h, const int* __restrict__ batch,
                       float* __restrict__ pooled, int N)
{
    int w = (blockIdx.x * blockDim.x + threadIdx.x) >> 5;
    if (w >= N) return;
    int lane = threadIdx.x & 31;
    int g = __ldg(batch + w);
    float4 v = *(const float4*)(h + (size_t)w * 128 + lane * 4);
    float* p = pooled + (size_t)g * 128 + lane * 4;
    asm volatile("red.global.add.v4.f32 [%0], {%1,%2,%3,%4};"
                 :: "l"(p), "f"(v.x), "f"(v.y), "f"(v.z), "f"(v.w)
                 : "memory");
}

// ---------------- decoder ----------------
__global__ void k_decoder(const float* __restrict__ pooled,
                          const float* __restrict__ w1, const float* __restrict__ b1,
                          const float* __restrict__ w2, const float* __restrict__ b2,
                          float* __restrict__ out)
{
    __shared__ float p[128];
    __shared__ float d1[128];
    int g = blockIdx.x;
    int t = threadIdx.x;
    p[t] = pooled[g * 128 + t];
    __syncthreads();
    float s = b1[t];
    #pragma unroll 8
    for (int k = 0; k < 128; ++k) s = fmaf(p[k], w1[k * 128 + t], s);
    d1[t] = fmaxf(s, 0.f);
    __syncthreads();
    if (t < 10) {
        float s2 = b2[t];
        #pragma unroll 8
        for (int j = 0; j < 128; ++j) s2 = fmaf(d1[j], w2[j * 10 + t], s2);
        out[g * 10 + t] = s2;
    }
}

// ---------------- driver ----------------
extern "C" void kernel_launch(void* const* d_in, const int* in_sizes, int n_in,
                              void* d_out, int out_size)
{
    const float* x      = (const float*)d_in[0];
    const int*   ei     = (const int*)d_in[1];
    const int*   batch  = (const int*)d_in[3];
    const float* enc_w1 = (const float*)d_in[4];
    const float* enc_b1 = (const float*)d_in[5];
    const float* enc_w2 = (const float*)d_in[6];
    const float* enc_b2 = (const float*)d_in[7];
    const float* conv_w = (const float*)d_in[8];
    const float* conv_b = (const float*)d_in[9];
    const float* dec_w1 = (const float*)d_in[10];
    const float* dec_b1 = (const float*)d_in[11];
    const float* dec_w2 = (const float*)d_in[12];
    const float* dec_b2 = (const float*)d_in[13];

    const int N = in_sizes[0] / HDIM;
    const int E = in_sizes[1] / 2;
    const int G = out_size / 10;

    float *bufA, *bufB, *bufC, *invs, *pooled;
    int *cnt, *off, *cursor, *bsum;
    float2* edge;
    cudaGetSymbolAddress((void**)&bufA, g_bufA);
    cudaGetSymbolAddress((void**)&bufB, g_bufB);
    cudaGetSymbolAddress((void**)&bufC, g_bufC);
    cudaGetSymbolAddress((void**)&invs, g_invs);
    cudaGetSymbolAddress((void**)&pooled, g_pooled);
    cudaGetSymbolAddress((void**)&cnt, g_cnt);
    cudaGetSymbolAddress((void**)&off, g_off);
    cudaGetSymbolAddress((void**)&cursor, g_cursor);
    cudaGetSymbolAddress((void**)&bsum, g_bsum);
    cudaGetSymbolAddress((void**)&edge, g_edge);

    const int* esrc = ei;
    const int* edst = ei + E;
    const int nb = (N + 1023) / 1024;
    const int ntiles = (N + PTILE - 1) / PTILE;

    cudaFuncSetAttribute(gemm_tf32p, cudaFuncAttributeMaxDynamicSharedMemorySize, GEMM_SMEM);

    // launches 0..2 (CSR head)
    k_zeros<<<(N + 255) / 256, 256>>>(cnt, pooled, N, G * 128);
    k_hist<<<(E + 255) / 256, 256>>>(edst, cnt, E);
    k_scan1<<<nb, 1024>>>(cnt, off, bsum, N);

    // launch 3: encoder GEMM 1  (profiled slot)
    gemm_tf32p<<<GEMM_GRID, 256, GEMM_SMEM>>>(x, enc_w1, enc_b1, bufC, N, ntiles, 0);

    // launches 4..5 (CSR tail)
    k_scan2<<<1, 1024>>>(bsum, nb);
    k_scan3_prep<<<nb, 1024>>>(off, bsum, cnt, cursor, invs, N, E);

    // encoder GEMM 2
    gemm_tf32p<<<GEMM_GRID, 256, GEMM_SMEM>>>(bufC, enc_w2, enc_b2, bufA, N, ntiles, 1);

    // edge records (needs invs)
    k_fill<<<(E + 255) / 256, 256>>>(esrc, edst, invs, cursor, edge, E);

    float* hcur  = bufA;
    float* hnext = bufC;
    float* hw    = bufB;

    for (int l = 0; l < 3; ++l) {
        gemm_tf32p<<<GEMM_GRID, 256, GEMM_SMEM>>>(hcur, conv_w + (size_t)l * 128 * 128,
                                                  conv_b + (size_t)l * 128, hw, N, ntiles,
                                                  l > 0 ? 1 : 0);
        k_aggregate<<<N, 128>>>(hw, edge, off, invs, hnext, N);
        float* t = hcur; hcur = hnext; hnext = t;
    }

    // global add pool (pooled zeroed at launch 0)
    k_pool<<<(N * 32 + 255) / 256, 256>>>(hcur, batch, pooled, N);

    // decoder
    k_decoder<<<G, 128>>>(pooled, dec_w1, dec_b1, dec_w2, dec_b2, (float*)d_out);
}